// round 2
// baseline (speedup 1.0000x reference)
#include <cuda_runtime.h>
#include <cuda_bf16.h>

// CausalSequenceCML: 16 fused steps of depthwise-causal-conv logistic CML.
// B=4, T=4096, C=512, K=4, STEPS=16.
//
// Round-2: pack adjacent time cells into f32x2 and use Blackwell packed
// fma.rn.f32x2 / mul.rn.f32x2 (FFMA2) — halves FMA-pipe instruction count.
// Negation via sign-bit XOR on the ALU pipe (bitwise-identical math).
//
// Block = 256 threads = 32 channels x 8 time-strips, 26 cells (13 pairs)
// per thread. Tile=208 (48 halo + 160 valid). State in registers; only 3
// boundary mapped-values per strip per step cross threads via smem.

#define Bdim 4
#define Tdim 4096
#define Cdim 512
#define NSTEPS 16
#define CC 32
#define SS 8
#define LL 26
#define NP (LL / 2)          // 13 packed pairs
#define TILE (SS * LL)       // 208
#define HALO 48              // 3 * NSTEPS
#define VALID (TILE - HALO)  // 160
#define NTILES ((Tdim + VALID - 1) / VALID)  // 26

typedef unsigned long long u64;

__device__ __forceinline__ u64 pack2(float lo, float hi) {
    u64 r;
    asm("mov.b64 %0, {%1, %2};" : "=l"(r) : "f"(lo), "f"(hi));
    return r;
}
__device__ __forceinline__ void unpack2(u64 v, float& lo, float& hi) {
    asm("mov.b64 {%0, %1}, %2;" : "=f"(lo), "=f"(hi) : "l"(v));
}
__device__ __forceinline__ u64 fma2(u64 a, u64 b, u64 c) {
    u64 d;
    asm("fma.rn.f32x2 %0, %1, %2, %3;" : "=l"(d) : "l"(a), "l"(b), "l"(c));
    return d;
}
__device__ __forceinline__ u64 mul2(u64 a, u64 b) {
    u64 d;
    asm("mul.rn.f32x2 %0, %1, %2;" : "=l"(d) : "l"(a), "l"(b));
    return d;
}

__global__ void __launch_bounds__(256, 2)
cml_kernel(const float* __restrict__ drive,
           const float* __restrict__ r,
           const float* __restrict__ eps,
           const float* __restrict__ beta,
           const float* __restrict__ Kc,
           float* __restrict__ out)
{
    __shared__ float bm[2][SS][3][CC];

    const int tid = threadIdx.x;
    const int c   = tid & (CC - 1);
    const int s   = tid >> 5;
    const int cg  = blockIdx.y * CC + c;
    const int b   = blockIdx.z;
    const int gt0 = (int)blockIdx.x * VALID - HALO;
    const int base = b * (Tdim * Cdim);

    const float rr = r[cg];
    const float ee = eps[cg];
    const float bb = beta[cg];
    const float k0 = Kc[cg * 4 + 0];
    const float k1 = Kc[cg * 4 + 1];
    const float k2 = Kc[cg * 4 + 2];
    const float k3 = Kc[cg * 4 + 3];
    const float onemb = 1.0f - bb;
    const float A  = onemb * (1.0f - ee);
    const float Bc = onemb * ee;
    const float w3 = fmaf(Bc, k3, A);
    const float w2 = Bc * k2;
    const float w1 = Bc * k1;
    const float w0 = Bc * k0;

    const u64 rr2 = pack2(rr, rr);
    const u64 w3p = pack2(w3, w3);
    const u64 w2p = pack2(w2, w2);
    const u64 w1p = pack2(w1, w1);
    const u64 w0p = pack2(w0, w0);
    const u64 SGN = 0x8000000080000000ULL;

    // load drive -> packed g, packed D = beta * drive
    u64 gp[NP], Dp[NP];
    const int ltbase = s * LL;
#pragma unroll
    for (int p = 0; p < NP; p++) {
        const int gta = gt0 + ltbase + 2 * p;
        const int gtb = gta + 1;
        float d0 = 0.0f, d1 = 0.0f;
        if (gta >= 0 && gta < Tdim) d0 = drive[base + gta * Cdim + cg];
        if (gtb >= 0 && gtb < Tdim) d1 = drive[base + gtb * Cdim + cg];
        gp[p] = pack2(d0, d1);
        Dp[p] = pack2(bb * d0, bb * d1);
    }

#pragma unroll 1
    for (int step = 0; step < NSTEPS; step++) {
        float* buf = &bm[step & 1][0][0][0];
        // boundary: mapped values of this strip's last 3 cells (23,24,25)
        {
            float g23, g24, g25, junk;
            unpack2(gp[NP - 2], junk, g23);
            unpack2(gp[NP - 1], g24, g25);
            float rg, mv;
            rg = rr * g23; mv = fmaf(-rg, g23, rg);
            buf[(s * 3 + 0) * CC + c] = mv;
            rg = rr * g24; mv = fmaf(-rg, g24, rg);
            buf[(s * 3 + 1) * CC + c] = mv;
            rg = rr * g25; mv = fmaf(-rg, g25, rg);
            buf[(s * 3 + 2) * CC + c] = mv;
        }
        __syncthreads();

        float m3s = 0.0f, m2s = 0.0f, m1s = 0.0f;
        if (s > 0) {
            m3s = buf[((s - 1) * 3 + 0) * CC + c];
            m2s = buf[((s - 1) * 3 + 1) * CC + c];
            m1s = buf[((s - 1) * 3 + 2) * CC + c];
        }
        // pm  = m0_pair[i-1]  (== m2_pair[i])
        // pm1 = m1_pair[i-1]  (== m3_pair[i])
        u64 pm  = pack2(m2s, m1s);
        u64 pm1 = pack2(m3s, m2s);

#pragma unroll
        for (int p = 0; p < NP; p++) {
            const u64 gv = gp[p];
            const u64 ng = gv ^ SGN;              // -g (ALU pipe)
            const u64 u  = mul2(rr2, gv);         // r*g
            const u64 m0 = fma2(u, ng, u);        // r*g*(1-g), exact fma
            float pml, pmh, m0l, m0h;
            unpack2(pm, pml, pmh);
            unpack2(m0, m0l, m0h);
            const u64 m1 = pack2(pmh, m0l);       // shifted-by-1 pair
            u64 acc = fma2(w3p, m0, Dp[p]);
            acc = fma2(w2p, m1, acc);
            acc = fma2(w1p, pm, acc);
            gp[p] = fma2(w0p, pm1, acc);
            pm1 = m1;
            pm  = m0;
        }
    }

    // clip + store valid region
#pragma unroll
    for (int p = 0; p < NP; p++) {
        float v0, v1;
        unpack2(gp[p], v0, v1);
        const int lta = ltbase + 2 * p;
        const int gta = gt0 + lta;
        if (lta >= HALO && gta < Tdim)
            out[base + gta * Cdim + cg] =
                fminf(fmaxf(v0, 1.0e-4f), 1.0f - 1.0e-4f);
        if (lta + 1 >= HALO && gta + 1 < Tdim)
            out[base + (gta + 1) * Cdim + cg] =
                fminf(fmaxf(v1, 1.0e-4f), 1.0f - 1.0e-4f);
    }
}

extern "C" void kernel_launch(void* const* d_in, const int* in_sizes, int n_in,
                              void* d_out, int out_size)
{
    const float* drive = (const float*)d_in[0];
    const float* r     = (const float*)d_in[1];
    const float* eps   = (const float*)d_in[2];
    const float* beta  = (const float*)d_in[3];
    const float* Kc    = (const float*)d_in[4];
    float* out = (float*)d_out;

    dim3 grid(NTILES, Cdim / CC, Bdim);   // 26 x 16 x 4
    cml_kernel<<<grid, CC * SS>>>(drive, r, eps, beta, Kc, out);
}

// round 3
// speedup vs baseline: 1.2900x; 1.2900x over previous
#include <cuda_runtime.h>
#include <cuda_bf16.h>

// CausalSequenceCML: 16 fused steps of depthwise-causal-conv logistic CML.
// B=4, T=4096, C=512, K=4, STEPS=16.
//
// Round-3: scalar path (f32x2 regressed on sm_100a), with
//  (a) r folded into conv weights -> m' = g*(1-g) = 1 FMA; 5 FMA-ops/cell-step
//  (b) SS=12 strips x LL=18 cells, 384 threads, launch_bounds(384,3)
//      -> ~56 regs, 36 warps/SM, halo amp 216/168 = 1.286.
//
// Only 3 boundary m' values per strip per step cross threads (smem,
// double-buffered), one __syncthreads per step.

#define Bdim 4
#define Tdim 4096
#define Cdim 512
#define NSTEPS 16
#define CC 32                // channels per block (warp-contiguous)
#define SS 12                // time strips per block
#define LL 18                // cells per thread
#define TILE (SS * LL)       // 216
#define HALO 48              // 3 * NSTEPS
#define VALID (TILE - HALO)  // 168
#define NTILES ((Tdim + VALID - 1) / VALID)  // 25

__global__ void __launch_bounds__(CC * SS, 3)
cml_kernel(const float* __restrict__ drive,
           const float* __restrict__ r,
           const float* __restrict__ eps,
           const float* __restrict__ beta,
           const float* __restrict__ Kc,
           float* __restrict__ out)
{
    // boundary m' values: [buf][strip][3][channel]
    __shared__ float bm[2][SS][3][CC];

    const int tid = threadIdx.x;
    const int c   = tid & (CC - 1);
    const int s   = tid >> 5;
    const int cg  = blockIdx.y * CC + c;
    const int b   = blockIdx.z;
    const int gt0 = (int)blockIdx.x * VALID - HALO;
    const int base = b * (Tdim * Cdim);

    // per-channel constants; fold r into the conv weights
    const float rr = r[cg];
    const float ee = eps[cg];
    const float bb = beta[cg];
    const float k0 = Kc[cg * 4 + 0];
    const float k1 = Kc[cg * 4 + 1];
    const float k2 = Kc[cg * 4 + 2];
    const float k3 = Kc[cg * 4 + 3];
    const float onemb = 1.0f - bb;
    const float A  = onemb * (1.0f - ee);    // coeff of m (non-conv part)
    const float Bc = onemb * ee;             // coeff of conv output
    const float v3 = fmaf(Bc, k3, A) * rr;   // coeff of m'[t]
    const float v2 = Bc * k2 * rr;           // m'[t-1]
    const float v1 = Bc * k1 * rr;           // m'[t-2]
    const float v0 = Bc * k0 * rr;           // m'[t-3]

    // load drive -> g init, D = beta * drive (step-invariant)
    float g[LL], D[LL];
    const int ltbase = s * LL;
#pragma unroll
    for (int i = 0; i < LL; i++) {
        const int gt = gt0 + ltbase + i;
        float d = 0.0f;
        if (gt >= 0 && gt < Tdim)
            d = drive[base + gt * Cdim + cg];
        g[i] = d;
        D[i] = bb * d;
    }

    float* const wbuf0 = &bm[0][s][0][0] + c;          // this strip's write slot
    float* const rbuf0 = &bm[0][(s > 0 ? s - 1 : 0)][0][0] + c;  // prev strip

#pragma unroll 1
    for (int step = 0; step < NSTEPS; step++) {
        const int off = (step & 1) ? (SS * 3 * CC) : 0;
        // boundary: m' of this strip's last 3 cells
#pragma unroll
        for (int j = 0; j < 3; j++) {
            const float gi = g[LL - 3 + j];
            wbuf0[off + j * CC] = fmaf(-gi, gi, gi);   // g*(1-g)
        }
        __syncthreads();

        float m3 = 0.0f, m2 = 0.0f, m1 = 0.0f;
        if (s > 0) {
            m3 = rbuf0[off + 0 * CC];
            m2 = rbuf0[off + 1 * CC];
            m1 = rbuf0[off + 2 * CC];
        }
        // main sweep: 5 FMA ops per cell
#pragma unroll
        for (int i = 0; i < LL; i++) {
            const float gi = g[i];
            const float m0 = fmaf(-gi, gi, gi);        // g*(1-g)
            float acc = fmaf(v3, m0, D[i]);
            acc = fmaf(v2, m1, acc);
            acc = fmaf(v1, m2, acc);
            g[i] = fmaf(v0, m3, acc);
            m3 = m2; m2 = m1; m1 = m0;
        }
    }

    // clip + store valid region
#pragma unroll
    for (int i = 0; i < LL; i++) {
        const int lt = ltbase + i;
        const int gt = gt0 + lt;
        if (lt >= HALO && gt < Tdim) {
            float v = fminf(fmaxf(g[i], 1.0e-4f), 1.0f - 1.0e-4f);
            out[base + gt * Cdim + cg] = v;
        }
    }
}

extern "C" void kernel_launch(void* const* d_in, const int* in_sizes, int n_in,
                              void* d_out, int out_size)
{
    const float* drive = (const float*)d_in[0];
    const float* r     = (const float*)d_in[1];
    const float* eps   = (const float*)d_in[2];
    const float* beta  = (const float*)d_in[3];
    const float* Kc    = (const float*)d_in[4];
    float* out = (float*)d_out;

    dim3 grid(NTILES, Cdim / CC, Bdim);   // 25 x 16 x 4
    cml_kernel<<<grid, CC * SS>>>(drive, r, eps, beta, Kc, out);
}